// round 2
// baseline (speedup 1.0000x reference)
#include <cuda_runtime.h>
#include <cuda_bf16.h>

// CenterLoss: loss = mean over (B,C) of distmat * one-hot(labels)
//           = (1/(B*C)) * sum_i ||x_i - centers[labels_i]||^2
// B=4096, C=20000, D=128. No GEMM required — pure gather + reduce.
// labels arrive as int32 (JAX downcasts int64 without x64 mode).

#define CL_BATCH 4096
#define CL_FEAT 128
#define CL_NCLASSES 20000
#define CL_ROWS_PER_BLOCK 8
#define CL_NBLOCKS (CL_BATCH / CL_ROWS_PER_BLOCK) // 512

__device__ float cl_g_partials[CL_NBLOCKS];

// One warp per batch row. 32 lanes * float4 = 128 floats.
__global__ void __launch_bounds__(256) cl_partial_kernel(
    const float* __restrict__ x,
    const int* __restrict__ labels,
    const float* __restrict__ centers)
{
    const int warp = threadIdx.x >> 5;
    const int lane = threadIdx.x & 31;
    const int row = blockIdx.x * CL_ROWS_PER_BLOCK + warp;

    const int lab = labels[row];

    const float4* __restrict__ xr = reinterpret_cast<const float4*>(x + (size_t)row * CL_FEAT);
    const float4* __restrict__ cr = reinterpret_cast<const float4*>(centers + (size_t)lab * CL_FEAT);

    float4 xv = xr[lane];
    float4 cv = cr[lane];

    float dx = xv.x - cv.x;
    float dy = xv.y - cv.y;
    float dz = xv.z - cv.z;
    float dw = xv.w - cv.w;
    float s = dx * dx + dy * dy + dz * dz + dw * dw;

    // warp reduction
    #pragma unroll
    for (int o = 16; o > 0; o >>= 1)
        s += __shfl_xor_sync(0xffffffffu, s, o);

    __shared__ float sm[CL_ROWS_PER_BLOCK];
    if (lane == 0) sm[warp] = s;
    __syncthreads();

    if (threadIdx.x == 0) {
        float t = 0.0f;
        #pragma unroll
        for (int i = 0; i < CL_ROWS_PER_BLOCK; i++) t += sm[i];
        cl_g_partials[blockIdx.x] = t;
    }
}

// Single block reduces the 512 partials deterministically.
__global__ void __launch_bounds__(512) cl_reduce_kernel(float* __restrict__ out)
{
    const int warp = threadIdx.x >> 5;
    const int lane = threadIdx.x & 31;

    float s = cl_g_partials[threadIdx.x];

    #pragma unroll
    for (int o = 16; o > 0; o >>= 1)
        s += __shfl_xor_sync(0xffffffffu, s, o);

    __shared__ float sm[16];
    if (lane == 0) sm[warp] = s;
    __syncthreads();

    if (threadIdx.x < 32) {
        float t = (threadIdx.x < 16) ? sm[threadIdx.x] : 0.0f;
        #pragma unroll
        for (int o = 8; o > 0; o >>= 1)
            t += __shfl_xor_sync(0xffffffffu, t, o);
        if (threadIdx.x == 0) {
            const float inv = 1.0f / ((float)CL_BATCH * (float)CL_NCLASSES);
            *out = t * inv;
        }
    }
}

extern "C" void kernel_launch(void* const* d_in, const int* in_sizes, int n_in,
                              void* d_out, int out_size)
{
    const float* x       = (const float*)d_in[0];
    const int*   labels  = (const int*)d_in[1];
    const float* centers = (const float*)d_in[2];
    float* out = (float*)d_out;

    cl_partial_kernel<<<CL_NBLOCKS, 256>>>(x, labels, centers);
    cl_reduce_kernel<<<1, 512>>>(out);
}